// round 9
// baseline (speedup 1.0000x reference)
#include <cuda_runtime.h>
#include <cuda_bf16.h>

#define HH 1024
#define WW 1024

static constexpr int NBLOCKS  = 1184;
static constexpr int NTHREADS = 256;

__device__ float        g_part[NBLOCKS];
__device__ unsigned int g_count = 0;

typedef unsigned long long ull;

__device__ __forceinline__ ull pk(float lo, float hi) {
    ull r; asm("mov.b64 %0, {%1, %2};" : "=l"(r) : "f"(lo), "f"(hi)); return r;
}
__device__ __forceinline__ ull sub2(ull a, ull b) {
    ull r; asm("sub.rn.f32x2 %0, %1, %2;" : "=l"(r) : "l"(a), "l"(b)); return r;
}
__device__ __forceinline__ ull fma2(ull a, ull b, ull c) {
    ull r; asm("fma.rn.f32x2 %0, %1, %2, %3;" : "=l"(r) : "l"(a), "l"(b), "l"(c)); return r;
}
__device__ __forceinline__ void unpk(ull v, float& lo, float& hi) {
    asm("mov.b64 {%0, %1}, %2;" : "=f"(lo), "=f"(hi) : "l"(v));
}

// Directed sum S for one row pair (c = row i, b = row i+1), per quad.
// Offsets: right (0,1); down (1,0); down-right (1,1); down-left re-indexed as
// (c_{k+1} - b_k) so only DOWN-shifts are needed. Edge duplicates per row pair
// (one col-0 vertical dup + one col-(W-1) vertical dup):
//   cr  := c.w at (lastq,ln31)  -> right tail term vanishes
//   br  := b.w at (lastq,ln31)  -> down-right tail becomes the col-(W-1) dup
//   crd := b.w at (lastq,ln31)  -> down-left tail vanishes
//   (c0-b0)^2 added explicitly at (firstq,ln0)   [scalar accs]
__device__ __forceinline__ void quadd2(const float4 c, const float4 b,
                                       float cr, float br, float crd, ull& acc2) {
    const ull vp01 = pk(c.x, c.y), vp23 = pk(c.z, c.w);
    const ull m01  = pk(c.y, c.z);
    ull d;
    d = sub2(vp01, m01);           acc2 = fma2(d, d, acc2);  // right
    d = sub2(vp23, pk(c.w, cr));   acc2 = fma2(d, d, acc2);
    d = sub2(vp01, pk(b.x, b.y));  acc2 = fma2(d, d, acc2);  // down
    d = sub2(vp23, pk(b.z, b.w));  acc2 = fma2(d, d, acc2);
    d = sub2(vp01, pk(b.y, b.z));  acc2 = fma2(d, d, acc2);  // down-right
    d = sub2(vp23, pk(b.w, br));   acc2 = fma2(d, d, acc2);
    d = sub2(m01,  pk(b.x, b.y));  acc2 = fma2(d, d, acc2);  // down-left (shifted)
    d = sub2(pk(c.w, crd), pk(b.z, b.w)); acc2 = fma2(d, d, acc2);
}

__device__ __forceinline__ void hdouble(const float4 c, float cr, ull& acc2) {
    ull d;
    d = sub2(pk(c.x, c.y), pk(c.y, c.z)); acc2 = fma2(d, d, acc2);
    d = sub2(pk(c.z, c.w), pk(c.w, cr));  acc2 = fma2(d, d, acc2);
}

__global__ __launch_bounds__(NTHREADS)
void lap_kernel(const float* __restrict__ f, float* __restrict__ out, int total_items) {
    ull   acc2 = 0;
    float accs = 0.0f;
    const int lane = threadIdx.x & 31;
    const int t0 = blockIdx.x * blockDim.x + threadIdx.x;

    // Column-quad invariant per thread (stride is a multiple of 256).
    const int  cq     = t0 & 255;
    const bool firstq = (cq == 0);
    const bool lastq  = (cq == 255);
    const bool ln31   = (lane == 31);
    const bool ln0    = (lane == 0);
    const bool fq0    = firstq && ln0;     // global col 0
    const bool lq31   = lastq && ln31;     // global col W-1
    const float* __restrict__ colp = f + (cq << 2);
    const int step = NBLOCKS * NTHREADS;

    // Work item: (plane, m) -> row pairs (2m,2m+1) and (2m+1,2m+2); m=511 handles
    // only pair (1022,1023) plus the doubled bottom-row horizontals.
    for (int t = t0; t < total_items; t += step) {
        const int m  = (t >> 8) & 511;
        const int pl = t >> 17;
        const float* __restrict__ p =
            colp + ((size_t)pl << 20) + ((size_t)(m << 1) << 10);

        const float4 r0 = *(const float4*)p;
        const float4 r1 = *(const float4*)(p + WW);

        if (m < 511) {
            const float4 r2 = *(const float4*)(p + 2 * WW);
            float h0, h1, h2;
            if (ln31 && !lastq) {               // right-halo patch loads (lane 31)
                h0 = p[4]; h1 = p[WW + 4]; h2 = p[2 * WW + 4];
            }
            float s0 = __shfl_down_sync(0xffffffffu, r0.x, 1);
            float s1 = __shfl_down_sync(0xffffffffu, r1.x, 1);
            float s2 = __shfl_down_sync(0xffffffffu, r2.x, 1);
            if (ln31) {
                s0 = lastq ? r0.w : h0;
                s1 = lastq ? r1.w : h1;
                s2 = lastq ? r2.w : h2;
            }
            const float crd0 = lq31 ? r1.w : s0;
            const float crd1 = lq31 ? r2.w : s1;

            quadd2(r0, r1, s0, s1, crd0, acc2);
            quadd2(r1, r2, s1, s2, crd1, acc2);

            if (fq0) {                          // col-0 vertical duplicates
                float d = r0.x - r1.x; accs += d * d;
                d = r1.x - r2.x;       accs += d * d;
            }
            if (m == 0) hdouble(r0, s0, acc2);  // top-row horizontals x2
        } else {
            float h0, h1;
            if (ln31 && !lastq) { h0 = p[4]; h1 = p[WW + 4]; }
            float s0 = __shfl_down_sync(0xffffffffu, r0.x, 1);
            float s1 = __shfl_down_sync(0xffffffffu, r1.x, 1);
            if (ln31) {
                s0 = lastq ? r0.w : h0;
                s1 = lastq ? r1.w : h1;
            }
            const float crd0 = lq31 ? r1.w : s0;

            quadd2(r0, r1, s0, s1, crd0, acc2); // pair (1022,1023)
            if (fq0) { const float d = r0.x - r1.x; accs += d * d; }
            hdouble(r1, s1, acc2);              // bottom-row horizontals x2
            hdouble(r1, s1, acc2);
        }
    }

    float lo, hi; unpk(acc2, lo, hi);
    float acc = accs + lo + hi;

    // ---- deterministic block reduction ----
    __shared__ float swarp[NTHREADS / 32];
    #pragma unroll
    for (int o = 16; o > 0; o >>= 1)
        acc += __shfl_down_sync(0xffffffffu, acc, o);
    if ((threadIdx.x & 31) == 0) swarp[threadIdx.x >> 5] = acc;
    __syncthreads();
    if (threadIdx.x < NTHREADS / 32) {
        float v = swarp[threadIdx.x];
        #pragma unroll
        for (int o = NTHREADS / 64; o > 0; o >>= 1)
            v += __shfl_down_sync(0xffu, v, o);
        if (threadIdx.x == 0) g_part[blockIdx.x] = v;
    }

    // ---- last-block final reduction ----
    __shared__ bool isLast;
    if (threadIdx.x == 0) {
        __threadfence();
        isLast = (atomicAdd(&g_count, 1u) == (unsigned)gridDim.x - 1u);
    }
    __syncthreads();
    if (isLast) {
        volatile float* gp = g_part;
        double v = 0.0;
        for (int idx = threadIdx.x; idx < NBLOCKS; idx += NTHREADS) v += (double)gp[idx];
        __shared__ double sd[NTHREADS];
        sd[threadIdx.x] = v;
        __syncthreads();
        #pragma unroll
        for (int o = NTHREADS / 2; o > 0; o >>= 1) {
            if (threadIdx.x < o) sd[threadIdx.x] += sd[threadIdx.x + o];
            __syncthreads();
        }
        if (threadIdx.x == 0) {
            out[0] = (float)(2.0 * sd[0]);
            g_count = 0;
        }
    }
}

extern "C" void kernel_launch(void* const* d_in, const int* in_sizes, int n_in,
                              void* d_out, int out_size) {
    const float* f = (const float*)d_in[0];
    const int n = in_sizes[0];
    const int planes = n >> 20;                 // 48
    const int total_items = planes << 17;       // planes * 512 m-blocks * 256 quads
    lap_kernel<<<NBLOCKS, NTHREADS>>>(f, (float*)d_out, total_items);
}